// round 16
// baseline (speedup 1.0000x reference)
#include <cuda_runtime.h>
#include <cuda_fp16.h>
#include <cstdint>

#define DD 128
#define N_MAX 50000

// scratch: aggregated features h = segment_sum(feature[src], dst)  (fp32)
static __device__ float4 g_h4[(size_t)N_MAX * (DD / 4)];
// fp16 copy of feature for the gather (halves scatter read traffic)
static __device__ uint2 g_fh2[(size_t)N_MAX * 32];   // 32 x 8B = 256B per row

// ---------------------------------------------------------------------------
// Index dtype detection (reference says int64, JAX x64-off emits int32)
// ---------------------------------------------------------------------------
__device__ __forceinline__ bool detect_i64(const void* p, int N) {
    const long long* q = (const long long*)p;
    bool ok = true;
    #pragma unroll
    for (int i = 0; i < 4; i++) {
        long long v = __ldg(&q[i]);
        if (v < 0 || v >= N) ok = false;
    }
    return ok;
}

__device__ __forceinline__ int load_idx(const void* p, int i, bool e64, int N) {
    long long v = e64 ? ((const long long*)p)[i] : (long long)((const int*)p)[i];
    if (v < 0) v = 0;
    if (v >= N) v = N - 1;
    return (int)v;
}

// ---------------------------------------------------------------------------
// Prep: zero g_h4 AND build fp16 feature copy in ONE kernel.
// Each thread: 4 float4 zeros + 4 float4->uint2 conversions.
// ---------------------------------------------------------------------------
__global__ void k_prep(const float* __restrict__ feat, int n4) {
    int i0 = (blockIdx.x * blockDim.x + threadIdx.x) * 4;
    float4 z = make_float4(0.f, 0.f, 0.f, 0.f);
    if (i0 + 3 < n4) {
        g_h4[i0 + 0] = z; g_h4[i0 + 1] = z;
        g_h4[i0 + 2] = z; g_h4[i0 + 3] = z;
        float4 v0 = __ldg(&reinterpret_cast<const float4*>(feat)[i0 + 0]);
        float4 v1 = __ldg(&reinterpret_cast<const float4*>(feat)[i0 + 1]);
        float4 v2 = __ldg(&reinterpret_cast<const float4*>(feat)[i0 + 2]);
        float4 v3 = __ldg(&reinterpret_cast<const float4*>(feat)[i0 + 3]);
        #pragma unroll
        for (int q = 0; q < 4; q++) {
            float4 v = (q == 0) ? v0 : (q == 1) ? v1 : (q == 2) ? v2 : v3;
            __half2 a = __floats2half2_rn(v.x, v.y);
            __half2 b = __floats2half2_rn(v.z, v.w);
            uint2 u;
            u.x = *reinterpret_cast<unsigned*>(&a);
            u.y = *reinterpret_cast<unsigned*>(&b);
            g_fh2[i0 + q] = u;
        }
    } else {
        for (int i = i0; i < n4; i++) {
            g_h4[i] = z;
            float4 v = __ldg(&reinterpret_cast<const float4*>(feat)[i]);
            __half2 a = __floats2half2_rn(v.x, v.y);
            __half2 b = __floats2half2_rn(v.z, v.w);
            uint2 u;
            u.x = *reinterpret_cast<unsigned*>(&a);
            u.y = *reinterpret_cast<unsigned*>(&b);
            g_fh2[i] = u;
        }
    }
}

// ---------------------------------------------------------------------------
// Scatter: one warp per FOUR edges; lane c gathers 4 halfs (8B), converts,
// one fp32 vec4 reduction atomic per edge. Read traffic halved vs fp32.
// ---------------------------------------------------------------------------
__device__ __forceinline__ void red4(float4* p, float x, float y, float z, float w) {
    asm volatile("red.global.add.v4.f32 [%0], {%1,%2,%3,%4};"
                 :: "l"(p), "f"(x), "f"(y), "f"(z), "f"(w) : "memory");
}

__device__ __forceinline__ void cvt_red(uint2 u, int d, int c) {
    __half2 a = *reinterpret_cast<__half2*>(&u.x);
    __half2 b = *reinterpret_cast<__half2*>(&u.y);
    float2 fa = __half22float2(a), fb = __half22float2(b);
    red4(g_h4 + (size_t)d * 32 + c, fa.x, fa.y, fb.x, fb.y);
}

__global__ void k_scatter(const void* __restrict__ src,
                          const void* __restrict__ dst,
                          int E, int N) {
    int gid = blockIdx.x * blockDim.x + threadIdx.x;
    int w = gid >> 5;
    int c = gid & 31;
    int e0 = w * 4;
    if (e0 >= E) return;
    bool e64 = detect_i64(src, N);

    if (e0 + 3 < E) {
        int s0 = load_idx(src, e0 + 0, e64, N), d0 = load_idx(dst, e0 + 0, e64, N);
        int s1 = load_idx(src, e0 + 1, e64, N), d1 = load_idx(dst, e0 + 1, e64, N);
        int s2 = load_idx(src, e0 + 2, e64, N), d2 = load_idx(dst, e0 + 2, e64, N);
        int s3 = load_idx(src, e0 + 3, e64, N), d3 = load_idx(dst, e0 + 3, e64, N);
        uint2 u0 = g_fh2[(size_t)s0 * 32 + c];
        uint2 u1 = g_fh2[(size_t)s1 * 32 + c];
        uint2 u2 = g_fh2[(size_t)s2 * 32 + c];
        uint2 u3 = g_fh2[(size_t)s3 * 32 + c];
        cvt_red(u0, d0, c);
        cvt_red(u1, d1, c);
        cvt_red(u2, d2, c);
        cvt_red(u3, d3, c);
    } else {
        for (int e = e0; e < E; e++) {
            int s = load_idx(src, e, e64, N);
            int d = load_idx(dst, e, e64, N);
            uint2 u = g_fh2[(size_t)s * 32 + c];
            cvt_red(u, d, c);
        }
    }
}

// ===========================================================================
// fp16 2-term split mma.sync GEMM + fused graphnorm/layernorm/relu
// A = ah + al (exact fp16 Dekker split); W = bh (single fp16 plane).
// Each warp owns a 16-row tile, full n=128. 8 warps/CTA, 2 CTAs/SM.
// ===========================================================================

#define WSTRIDE 272                       // bytes per k-row (136 fp16)
#define SM_GAMMA 0
#define SM_BETA  512
#define WH_OFF   1024
#define A_OFF    (WH_OFF + 128 * WSTRIDE) // 35840
#define A_WARP   (2 * 16 * WSTRIDE)       // 8704 per warp (hi+lo planes)
#define NWARP    8
#define SM_TOTAL (A_OFF + NWARP * A_WARP) // 105472 bytes

__device__ __forceinline__ uint32_t smem_u32(const void* p) {
    uint32_t a;
    asm("{ .reg .u64 t; cvta.to.shared.u64 t, %1; cvt.u32.u64 %0, t; }"
        : "=r"(a) : "l"(p));
    return a;
}

// fp16 Dekker split of a float pair: hi = rn(x), lo = rn(x - hi)
__device__ __forceinline__ void split2h(float a, float b, unsigned& hi, unsigned& lo) {
    __half2 h = __floats2half2_rn(a, b);
    hi = *reinterpret_cast<unsigned*>(&h);
    float ra = a - __half2float(__low2half(h));
    float rb = b - __half2float(__high2half(h));
    __half2 l = __floats2half2_rn(ra, rb);
    lo = *reinterpret_cast<unsigned*>(&l);
}

__device__ __forceinline__ unsigned pk_h(float a, float b) {
    __half2 h = __floats2half2_rn(a, b);
    return *reinterpret_cast<unsigned*>(&h);
}

__device__ __forceinline__ void ldsm4(uint32_t addr, uint32_t r[4]) {
    asm volatile("ldmatrix.sync.aligned.m8n8.x4.shared.b16 {%0,%1,%2,%3}, [%4];"
                 : "=r"(r[0]), "=r"(r[1]), "=r"(r[2]), "=r"(r[3]) : "r"(addr));
}

__device__ __forceinline__ void mma_f16(float d[4], const uint32_t a[4],
                                        uint32_t b0, uint32_t b1) {
    asm volatile(
        "mma.sync.aligned.m16n8k16.row.col.f32.f16.f16.f32 "
        "{%0,%1,%2,%3}, {%4,%5,%6,%7}, {%8,%9}, {%0,%1,%2,%3};"
        : "+f"(d[0]), "+f"(d[1]), "+f"(d[2]), "+f"(d[3])
        : "r"(a[0]), "r"(a[1]), "r"(a[2]), "r"(a[3]), "r"(b0), "r"(b1));
}

__global__ __launch_bounds__(NWARP * 32, 2) void k_mma_norm(
    const float* __restrict__ snorm,
    const float* __restrict__ Wg,     // [128,128] row-major W[j][k]
    const float* __restrict__ gamma,
    const float* __restrict__ beta,
    float* __restrict__ out,
    int N)
{
    extern __shared__ char smem[];
    uint32_t sb = smem_u32(smem);
    int tid = threadIdx.x;
    int lane = tid & 31;
    int warp = tid >> 5;

    if (tid < 128) {
        ((float*)(smem + SM_GAMMA))[tid] = gamma[tid];
        ((float*)(smem + SM_BETA))[tid]  = beta[tid];
    }

    // Stage W once: single fp16 plane, layout [j][k] (row j = output col).
    for (int idx = tid; idx < 128 * 32; idx += NWARP * 32) {
        int j = idx >> 5, q = idx & 31;
        float4 v = reinterpret_cast<const float4*>(Wg)[j * 32 + q];
        uint2 uh;
        uh.x = pk_h(v.x, v.y);
        uh.y = pk_h(v.z, v.w);
        *reinterpret_cast<uint2*>(smem + WH_OFF + j * WSTRIDE + q * 8) = uh;
    }
    __syncthreads();

    char* Ah = smem + A_OFF + warp * A_WARP;
    char* Al = Ah + 16 * WSTRIDE;
    uint32_t AhU = sb + A_OFF + warp * A_WARP;
    uint32_t AlU = AhU + 16 * WSTRIDE;

    const int arow  = (lane & 7) + ((lane >> 3) & 1) * 8;
    const int ahalf = (lane >> 4) & 1;
    const int bn    = (lane & 7) + ((lane >> 4) & 1) * 8;
    const int bkh   = (lane >> 3) & 1;

    const int ntiles = (N + 15) >> 4;

    for (int tile = blockIdx.x * NWARP + warp; tile < ntiles;
         tile += gridDim.x * NWARP) {
        int row0 = tile * 16;

        // ---- stage A (16 rows) as hi/lo fp16 planes ----
        #pragma unroll 4
        for (int r = 0; r < 16; r++) {
            int row = row0 + r;
            if (row >= N) row = N - 1;
            float4 v = g_h4[(size_t)row * 32 + lane];
            unsigned h01, l01, h23, l23;
            split2h(v.x, v.y, h01, l01);
            split2h(v.z, v.w, h23, l23);
            uint2 uh; uh.x = h01; uh.y = h23;
            uint2 ul; ul.x = l01; ul.y = l23;
            *reinterpret_cast<uint2*>(Ah + r * WSTRIDE + lane * 8) = uh;
            *reinterpret_cast<uint2*>(Al + r * WSTRIDE + lane * 8) = ul;
        }
        __syncwarp();

        float acc[16][4];
        #pragma unroll
        for (int n = 0; n < 16; n++)
            #pragma unroll
            for (int u = 0; u < 4; u++) acc[n][u] = 0.f;

        #pragma unroll 1
        for (int ks = 0; ks < 8; ks++) {
            int k0 = ks * 16;
            uint32_t ah[4], al[4];
            uint32_t aoff = (uint32_t)(arow * WSTRIDE + (k0 + ahalf * 8) * 2);
            ldsm4(AhU + aoff, ah);
            ldsm4(AlU + aoff, al);
            uint32_t bh[8][4];
            #pragma unroll
            for (int p = 0; p < 8; p++) {
                int n = p * 16 + bn;
                uint32_t boff = (uint32_t)(n * WSTRIDE + (k0 + bkh * 8) * 2);
                ldsm4(sb + WH_OFF + boff, bh[p]);
            }
            #pragma unroll
            for (int p = 0; p < 8; p++) {
                mma_f16(acc[2 * p + 0], ah, bh[p][0], bh[p][1]);
                mma_f16(acc[2 * p + 1], ah, bh[p][2], bh[p][3]);
            }
            #pragma unroll
            for (int p = 0; p < 8; p++) {
                mma_f16(acc[2 * p + 0], al, bh[p][0], bh[p][1]);
                mma_f16(acc[2 * p + 1], al, bh[p][2], bh[p][3]);
            }
        }

        // ---- epilogue: snorm -> layernorm -> affine -> relu ----
        int r1 = row0 + (lane >> 2);
        int r2 = r1 + 8;
        float s1 = (r1 < N) ? __ldg(snorm + r1) : 0.f;
        float s2 = (r2 < N) ? __ldg(snorm + r2) : 0.f;
        float sum1 = 0.f, sq1 = 0.f, sum2 = 0.f, sq2 = 0.f;
        #pragma unroll
        for (int n = 0; n < 16; n++) {
            acc[n][0] *= s1; acc[n][1] *= s1;
            acc[n][2] *= s2; acc[n][3] *= s2;
            sum1 += acc[n][0] + acc[n][1];
            sq1  += acc[n][0] * acc[n][0] + acc[n][1] * acc[n][1];
            sum2 += acc[n][2] + acc[n][3];
            sq2  += acc[n][2] * acc[n][2] + acc[n][3] * acc[n][3];
        }
        #pragma unroll
        for (int o = 1; o <= 2; o <<= 1) {
            sum1 += __shfl_xor_sync(0xffffffffu, sum1, o);
            sq1  += __shfl_xor_sync(0xffffffffu, sq1,  o);
            sum2 += __shfl_xor_sync(0xffffffffu, sum2, o);
            sq2  += __shfl_xor_sync(0xffffffffu, sq2,  o);
        }
        float m1 = sum1 * (1.0f / 128.0f);
        float v1 = sq1 * (1.0f / 128.0f) - m1 * m1;
        float rs1 = rsqrtf(v1 + 1e-5f);
        float m2 = sum2 * (1.0f / 128.0f);
        float v2 = sq2 * (1.0f / 128.0f) - m2 * m2;
        float rs2 = rsqrtf(v2 + 1e-5f);

        const float* sg  = (const float*)(smem + SM_GAMMA);
        const float* sbt = (const float*)(smem + SM_BETA);
        #pragma unroll
        for (int n = 0; n < 16; n++) {
            int c = n * 8 + (lane & 3) * 2;
            if (r1 < N) {
                float2 o;
                o.x = fmaxf((acc[n][0] - m1) * rs1 * sg[c]     + sbt[c],     0.f);
                o.y = fmaxf((acc[n][1] - m1) * rs1 * sg[c + 1] + sbt[c + 1], 0.f);
                *reinterpret_cast<float2*>(out + (size_t)r1 * DD + c) = o;
            }
            if (r2 < N) {
                float2 o;
                o.x = fmaxf((acc[n][2] - m2) * rs2 * sg[c]     + sbt[c],     0.f);
                o.y = fmaxf((acc[n][3] - m2) * rs2 * sg[c + 1] + sbt[c + 1], 0.f);
                *reinterpret_cast<float2*>(out + (size_t)r2 * DD + c) = o;
            }
        }
        __syncwarp();
    }
}

// ---------------------------------------------------------------------------
extern "C" void kernel_launch(void* const* d_in, const int* in_sizes, int n_in,
                              void* d_out, int out_size) {
    const float* feature = (const float*)d_in[0];
    const float* snorm   = (const float*)d_in[1];
    const float* Wg      = (const float*)d_in[2];
    const float* gamma   = (const float*)d_in[3];
    const float* beta    = (const float*)d_in[4];
    const void*  src     = d_in[5];
    const void*  dst     = d_in[6];
    int N = in_sizes[1];
    int E = in_sizes[5];
    float* out = (float*)d_out;

    // 1) fused: zero accumulator + build fp16 feature copy
    int n4 = N * 32;
    int pthreads = (n4 + 3) / 4;
    k_prep<<<(pthreads + 255) / 256, 256>>>(feature, n4);

    // 2) gather (fp16) + fp32 vector-atomic scatter: one warp per FOUR edges
    int nq = (E + 3) / 4;
    long long tt = (long long)nq * 32;
    k_scatter<<<(int)((tt + 255) / 256), 256>>>(src, dst, E, N);

    // 3) fp16 2-term split mma.sync GEMM + graphnorm + layernorm + relu
    cudaFuncSetAttribute(k_mma_norm,
                         cudaFuncAttributeMaxDynamicSharedMemorySize, SM_TOTAL);
    k_mma_norm<<<296, NWARP * 32, SM_TOTAL>>>(snorm, Wg, gamma, beta, out, N);
}

// round 17
// speedup vs baseline: 1.0829x; 1.0829x over previous
#include <cuda_runtime.h>
#include <cuda_fp16.h>
#include <cstdint>

#define DD 128
#define N_MAX 50000

// scratch: aggregated features h = segment_sum(feature[src], dst)
static __device__ float4 g_h4[(size_t)N_MAX * (DD / 4)];

// ---------------------------------------------------------------------------
// Index dtype detection (reference says int64, JAX x64-off emits int32)
// ---------------------------------------------------------------------------
__device__ __forceinline__ bool detect_i64(const void* p, int N) {
    const long long* q = (const long long*)p;
    bool ok = true;
    #pragma unroll
    for (int i = 0; i < 4; i++) {
        long long v = __ldg(&q[i]);
        if (v < 0 || v >= N) ok = false;
    }
    return ok;
}

__device__ __forceinline__ int load_idx(const void* p, int i, bool e64, int N) {
    long long v = e64 ? ((const long long*)p)[i] : (long long)((const int*)p)[i];
    if (v < 0) v = 0;
    if (v >= N) v = N - 1;
    return (int)v;
}

// ---------------------------------------------------------------------------
// Scatter: one warp per EIGHT edges, lane c owns float4 column c.
// 8 independent gather+RED chains per thread for maximum MLP.
// ---------------------------------------------------------------------------
__device__ __forceinline__ void red4v(float4* p, float4 v) {
    asm volatile("red.global.add.v4.f32 [%0], {%1,%2,%3,%4};"
                 :: "l"(p), "f"(v.x), "f"(v.y), "f"(v.z), "f"(v.w) : "memory");
}

__global__ void k_scatter(const float* __restrict__ feat,
                          const void* __restrict__ src,
                          const void* __restrict__ dst,
                          int E, int N) {
    int gid = blockIdx.x * blockDim.x + threadIdx.x;
    int w = gid >> 5;
    int c = gid & 31;
    int e0 = w * 8;
    if (e0 >= E) return;
    bool e64 = detect_i64(src, N);
    const float4* f4 = reinterpret_cast<const float4*>(feat);

    if (e0 + 7 < E) {
        int s[8], d[8];
        #pragma unroll
        for (int q = 0; q < 8; q++) {
            s[q] = load_idx(src, e0 + q, e64, N);
            d[q] = load_idx(dst, e0 + q, e64, N);
        }
        float4 v[8];
        #pragma unroll
        for (int q = 0; q < 8; q++)
            v[q] = f4[(size_t)s[q] * 32 + c];
        #pragma unroll
        for (int q = 0; q < 8; q++)
            red4v(g_h4 + (size_t)d[q] * 32 + c, v[q]);
    } else {
        for (int e = e0; e < E; e++) {
            int s = load_idx(src, e, e64, N);
            int d = load_idx(dst, e, e64, N);
            float4 v = f4[(size_t)s * 32 + c];
            red4v(g_h4 + (size_t)d * 32 + c, v);
        }
    }
}

// ===========================================================================
// fp16 2-term split mma.sync GEMM + fused graphnorm/layernorm/relu
// A = ah + al (exact fp16 Dekker split); W = bh (single fp16 plane).
// Each warp owns a 16-row tile, full n=128. 8 warps/CTA, 2 CTAs/SM.
// ===========================================================================

#define WSTRIDE 272                       // bytes per k-row (136 fp16)
#define SM_GAMMA 0
#define SM_BETA  512
#define WH_OFF   1024
#define A_OFF    (WH_OFF + 128 * WSTRIDE) // 35840
#define A_WARP   (2 * 16 * WSTRIDE)       // 8704 per warp (hi+lo planes)
#define NWARP    8
#define SM_TOTAL (A_OFF + NWARP * A_WARP) // 105472 bytes

__device__ __forceinline__ uint32_t smem_u32(const void* p) {
    uint32_t a;
    asm("{ .reg .u64 t; cvta.to.shared.u64 t, %1; cvt.u32.u64 %0, t; }"
        : "=r"(a) : "l"(p));
    return a;
}

// fp16 Dekker split of a float pair: hi = rn(x), lo = rn(x - hi)
__device__ __forceinline__ void split2h(float a, float b, unsigned& hi, unsigned& lo) {
    __half2 h = __floats2half2_rn(a, b);
    hi = *reinterpret_cast<unsigned*>(&h);
    float ra = a - __half2float(__low2half(h));
    float rb = b - __half2float(__high2half(h));
    __half2 l = __floats2half2_rn(ra, rb);
    lo = *reinterpret_cast<unsigned*>(&l);
}

__device__ __forceinline__ unsigned pk_h(float a, float b) {
    __half2 h = __floats2half2_rn(a, b);
    return *reinterpret_cast<unsigned*>(&h);
}

__device__ __forceinline__ void ldsm4(uint32_t addr, uint32_t r[4]) {
    asm volatile("ldmatrix.sync.aligned.m8n8.x4.shared.b16 {%0,%1,%2,%3}, [%4];"
                 : "=r"(r[0]), "=r"(r[1]), "=r"(r[2]), "=r"(r[3]) : "r"(addr));
}

__device__ __forceinline__ void mma_f16(float d[4], const uint32_t a[4],
                                        uint32_t b0, uint32_t b1) {
    asm volatile(
        "mma.sync.aligned.m16n8k16.row.col.f32.f16.f16.f32 "
        "{%0,%1,%2,%3}, {%4,%5,%6,%7}, {%8,%9}, {%0,%1,%2,%3};"
        : "+f"(d[0]), "+f"(d[1]), "+f"(d[2]), "+f"(d[3])
        : "r"(a[0]), "r"(a[1]), "r"(a[2]), "r"(a[3]), "r"(b0), "r"(b1));
}

__global__ __launch_bounds__(NWARP * 32, 2) void k_mma_norm(
    const float* __restrict__ snorm,
    const float* __restrict__ Wg,     // [128,128] row-major W[j][k]
    const float* __restrict__ gamma,
    const float* __restrict__ beta,
    float* __restrict__ out,
    int N)
{
    extern __shared__ char smem[];
    uint32_t sb = smem_u32(smem);
    int tid = threadIdx.x;
    int lane = tid & 31;
    int warp = tid >> 5;

    if (tid < 128) {
        ((float*)(smem + SM_GAMMA))[tid] = gamma[tid];
        ((float*)(smem + SM_BETA))[tid]  = beta[tid];
    }

    // Stage W once: single fp16 plane, layout [j][k] (row j = output col).
    for (int idx = tid; idx < 128 * 32; idx += NWARP * 32) {
        int j = idx >> 5, q = idx & 31;
        float4 v = reinterpret_cast<const float4*>(Wg)[j * 32 + q];
        uint2 uh;
        uh.x = pk_h(v.x, v.y);
        uh.y = pk_h(v.z, v.w);
        *reinterpret_cast<uint2*>(smem + WH_OFF + j * WSTRIDE + q * 8) = uh;
    }
    __syncthreads();

    char* Ah = smem + A_OFF + warp * A_WARP;
    char* Al = Ah + 16 * WSTRIDE;
    uint32_t AhU = sb + A_OFF + warp * A_WARP;
    uint32_t AlU = AhU + 16 * WSTRIDE;

    const int arow  = (lane & 7) + ((lane >> 3) & 1) * 8;
    const int ahalf = (lane >> 4) & 1;
    const int bn    = (lane & 7) + ((lane >> 4) & 1) * 8;
    const int bkh   = (lane >> 3) & 1;

    const int ntiles = (N + 15) >> 4;

    for (int tile = blockIdx.x * NWARP + warp; tile < ntiles;
         tile += gridDim.x * NWARP) {
        int row0 = tile * 16;

        // ---- stage A (16 rows) as hi/lo fp16 planes ----
        #pragma unroll 4
        for (int r = 0; r < 16; r++) {
            int row = row0 + r;
            if (row >= N) row = N - 1;
            float4 v = g_h4[(size_t)row * 32 + lane];
            unsigned h01, l01, h23, l23;
            split2h(v.x, v.y, h01, l01);
            split2h(v.z, v.w, h23, l23);
            uint2 uh; uh.x = h01; uh.y = h23;
            uint2 ul; ul.x = l01; ul.y = l23;
            *reinterpret_cast<uint2*>(Ah + r * WSTRIDE + lane * 8) = uh;
            *reinterpret_cast<uint2*>(Al + r * WSTRIDE + lane * 8) = ul;
        }
        __syncwarp();

        float acc[16][4];
        #pragma unroll
        for (int n = 0; n < 16; n++)
            #pragma unroll
            for (int u = 0; u < 4; u++) acc[n][u] = 0.f;

        #pragma unroll 1
        for (int ks = 0; ks < 8; ks++) {
            int k0 = ks * 16;
            uint32_t ah[4], al[4];
            uint32_t aoff = (uint32_t)(arow * WSTRIDE + (k0 + ahalf * 8) * 2);
            ldsm4(AhU + aoff, ah);
            ldsm4(AlU + aoff, al);
            uint32_t bh[8][4];
            #pragma unroll
            for (int p = 0; p < 8; p++) {
                int n = p * 16 + bn;
                uint32_t boff = (uint32_t)(n * WSTRIDE + (k0 + bkh * 8) * 2);
                ldsm4(sb + WH_OFF + boff, bh[p]);
            }
            #pragma unroll
            for (int p = 0; p < 8; p++) {
                mma_f16(acc[2 * p + 0], ah, bh[p][0], bh[p][1]);
                mma_f16(acc[2 * p + 1], ah, bh[p][2], bh[p][3]);
            }
            #pragma unroll
            for (int p = 0; p < 8; p++) {
                mma_f16(acc[2 * p + 0], al, bh[p][0], bh[p][1]);
                mma_f16(acc[2 * p + 1], al, bh[p][2], bh[p][3]);
            }
        }

        // ---- epilogue: snorm -> layernorm -> affine -> relu ----
        int r1 = row0 + (lane >> 2);
        int r2 = r1 + 8;
        float s1 = (r1 < N) ? __ldg(snorm + r1) : 0.f;
        float s2 = (r2 < N) ? __ldg(snorm + r2) : 0.f;
        float sum1 = 0.f, sq1 = 0.f, sum2 = 0.f, sq2 = 0.f;
        #pragma unroll
        for (int n = 0; n < 16; n++) {
            acc[n][0] *= s1; acc[n][1] *= s1;
            acc[n][2] *= s2; acc[n][3] *= s2;
            sum1 += acc[n][0] + acc[n][1];
            sq1  += acc[n][0] * acc[n][0] + acc[n][1] * acc[n][1];
            sum2 += acc[n][2] + acc[n][3];
            sq2  += acc[n][2] * acc[n][2] + acc[n][3] * acc[n][3];
        }
        #pragma unroll
        for (int o = 1; o <= 2; o <<= 1) {
            sum1 += __shfl_xor_sync(0xffffffffu, sum1, o);
            sq1  += __shfl_xor_sync(0xffffffffu, sq1,  o);
            sum2 += __shfl_xor_sync(0xffffffffu, sum2, o);
            sq2  += __shfl_xor_sync(0xffffffffu, sq2,  o);
        }
        float m1 = sum1 * (1.0f / 128.0f);
        float v1 = sq1 * (1.0f / 128.0f) - m1 * m1;
        float rs1 = rsqrtf(v1 + 1e-5f);
        float m2 = sum2 * (1.0f / 128.0f);
        float v2 = sq2 * (1.0f / 128.0f) - m2 * m2;
        float rs2 = rsqrtf(v2 + 1e-5f);

        const float* sg  = (const float*)(smem + SM_GAMMA);
        const float* sbt = (const float*)(smem + SM_BETA);
        #pragma unroll
        for (int n = 0; n < 16; n++) {
            int c = n * 8 + (lane & 3) * 2;
            if (r1 < N) {
                float2 o;
                o.x = fmaxf((acc[n][0] - m1) * rs1 * sg[c]     + sbt[c],     0.f);
                o.y = fmaxf((acc[n][1] - m1) * rs1 * sg[c + 1] + sbt[c + 1], 0.f);
                *reinterpret_cast<float2*>(out + (size_t)r1 * DD + c) = o;
            }
            if (r2 < N) {
                float2 o;
                o.x = fmaxf((acc[n][2] - m2) * rs2 * sg[c]     + sbt[c],     0.f);
                o.y = fmaxf((acc[n][3] - m2) * rs2 * sg[c + 1] + sbt[c + 1], 0.f);
                *reinterpret_cast<float2*>(out + (size_t)r2 * DD + c) = o;
            }
        }
        __syncwarp();
    }
}

// ---------------------------------------------------------------------------
extern "C" void kernel_launch(void* const* d_in, const int* in_sizes, int n_in,
                              void* d_out, int out_size) {
    const float* feature = (const float*)d_in[0];
    const float* snorm   = (const float*)d_in[1];
    const float* Wg      = (const float*)d_in[2];
    const float* gamma   = (const float*)d_in[3];
    const float* beta    = (const float*)d_in[4];
    const void*  src     = d_in[5];
    const void*  dst     = d_in[6];
    int N = in_sizes[1];
    int E = in_sizes[5];
    float* out = (float*)d_out;

    // 1) zero accumulator via async memset (graph-capturable memset node)
    void* hptr = nullptr;
    cudaGetSymbolAddress(&hptr, g_h4);
    cudaMemsetAsync(hptr, 0, (size_t)N * DD * sizeof(float), 0);

    // 2) gather + vector-atomic scatter: one warp per EIGHT edges
    int no = (E + 7) / 8;
    long long tt = (long long)no * 32;
    k_scatter<<<(int)((tt + 255) / 256), 256>>>(feature, src, dst, E, N);

    // 3) fp16 2-term split mma.sync GEMM + graphnorm + layernorm + relu
    cudaFuncSetAttribute(k_mma_norm,
                         cudaFuncAttributeMaxDynamicSharedMemorySize, SM_TOTAL);
    k_mma_norm<<<296, NWARP * 32, SM_TOTAL>>>(snorm, Wg, gamma, beta, out, N);
}